// round 4
// baseline (speedup 1.0000x reference)
#include <cuda_runtime.h>

// Problem constants
#define NCTA   128
#define TPB    512
#define NB     512
#define BT     4       // batch elements per CTA
#define NC     184     // cities
#define HH     32      // hidden
#define IND    14      // in_dim
#define DD     15      // in_dim + 1
#define NPRED  24
#define NHIST  24
#define NFEAT  13      // in_dim - 1
#define FTOT   48      // hist + pred

// Global scratch (per-CTA private slices; same-CTA produce/consume only)
__device__ float g_y0[(size_t)NCTA * NC * BT * 64];

// Shared memory layout (float offsets)
#define OFF_X    0        // 184*16*4 = 11776   x tile [c][k(16)][b], slot15 = zero pad
#define OFF_XIN  11776    // 2*256              L1 staged input [dir][k(64)][b]
#define OFF_GP   12288    // 2*2*128*2 = 1024   gate sums as u64 [dir][bpair][row]
#define OFF_H    13312    // 4*32*4   = 512     h state [ld][k][b]
#define OFF_C    13824    // 4*32*4   = 512     c state [ld][k][b]
#define OFF_XN   14336    // 184*4    = 736     xn [c][b]
#define OFF_GX   15072    // 4*96     = 384
#define OFF_GH   15456    // 16*96    = 1536
#define OFF_U    16992    // 4*16     = 64
#define OFF_MP   17056    // 2*184*4  = 1472    MLP partials
#define SMEM_FLOATS 18528 // 74,112 bytes

typedef unsigned long long u64;

__device__ __forceinline__ u64 pk2(float w) {
    u64 r;
    asm("mov.b64 %0, {%1, %1};" : "=l"(r) : "f"(w));
    return r;
}
__device__ __forceinline__ void ffma2(u64& a, u64 x, u64 w) {
    asm("fma.rn.f32x2 %0, %1, %2, %0;" : "+l"(a) : "l"(x), "l"(w));
}
__device__ __forceinline__ u64 addx2(u64 a, u64 b) {
    u64 r;
    asm("add.rn.f32x2 %0, %1, %2;" : "=l"(r) : "l"(a), "l"(b));
    return r;
}
__device__ __forceinline__ float2 unpk(u64 a) {
    float2 f;
    asm("mov.b64 {%0, %1}, %2;" : "=f"(f.x), "=f"(f.y) : "l"(a));
    return f;
}
__device__ __forceinline__ float sigf(float x) {
    return __fdividef(1.0f, 1.0f + __expf(-x));
}
__device__ __forceinline__ float tanhfast(float x) {
    x = fminf(fmaxf(x, -15.0f), 15.0f);
    float e = __expf(2.0f * x);
    return __fdividef(e - 1.0f, e + 1.0f);
}
__device__ __forceinline__ void dbar(int dir) {
    asm volatile("bar.sync %0, %1;" :: "r"(1 + dir), "r"(256) : "memory");
}

// in-warp reduce-scatter over 4 ksplit lanes: lane ks ends with sum for
// v = ks, where v = r*2 + bpair (r = row within pair). bias added once.
__device__ __forceinline__ u64 redscat(u64 a0, u64 a1, u64 a2, u64 a3,
                                       int ks, float bias) {
    bool hi2 = (ks & 2) != 0;
    u64 s0 = hi2 ? a0 : a2, s1 = hi2 ? a1 : a3;
    u64 k0 = hi2 ? a2 : a0, k1 = hi2 ? a3 : a1;
    u64 r0 = __shfl_xor_sync(0xffffffffu, s0, 2);
    u64 r1 = __shfl_xor_sync(0xffffffffu, s1, 2);
    u64 b0_ = addx2(k0, r0), b1_ = addx2(k1, r1);
    bool hi1 = (ks & 1) != 0;
    u64 s = hi1 ? b0_ : b1_, k = hi1 ? b1_ : b0_;
    u64 r = __shfl_xor_sync(0xffffffffu, s, 1);
    return addx2(addx2(k, r), pk2(bias));
}

__global__ void __launch_bounds__(TPB, 1)
bilstm_kernel(const float* __restrict__ rain_hist,
              const float* __restrict__ feature,
              const float* __restrict__ h0,
              const float* __restrict__ c0,
              const float* __restrict__ W_mlp,
              const float* __restrict__ b_mlp,
              const float* __restrict__ Wih_g,
              const float* __restrict__ Whh_g,
              const float* __restrict__ b_ih_g,
              const float* __restrict__ b_hh_g,
              const float* __restrict__ Wih0,
              const float* __restrict__ Whh0,
              const float* __restrict__ b0,
              const float* __restrict__ Wih1,
              const float* __restrict__ Whh1,
              const float* __restrict__ b1,
              const float* __restrict__ W_fc,
              const float* __restrict__ b_fc,
              float* __restrict__ out)
{
    extern __shared__ float sm[];
    float* sX   = sm + OFF_X;
    float* sXin = sm + OFF_XIN;
    float* sGPf = sm + OFF_GP;
    u64*   sGPq = (u64*)sGPf;
    float* sH   = sm + OFF_H;
    float* sCst = sm + OFF_C;
    float* sXN  = sm + OFF_XN;
    float* sGX  = sm + OFF_GX;
    float* sGH  = sm + OFF_GH;
    float* sU   = sm + OFF_U;
    float* sMP  = sm + OFF_MP;

    const int tid  = threadIdx.x;
    const int cta  = blockIdx.x;
    const int bg   = cta * BT;
    const int lane = tid & 31;
    const int wid  = tid >> 5;          // 0..15
    const int dir  = wid >> 3;          // warps 0-7 dir0, 8-15 dir1
    const int w8   = wid & 7;           // 0..7 within dir
    const int rg   = lane >> 2;         // rowgroup 0..7
    const int ks   = lane & 3;          // k-split 0..3
    const int rgG  = w8 * 8 + rg;       // 0..63
    const int row0 = rgG * 2;           // first of 2 rows (within dir)
    const int rowOut = rgG * 2 + (ks >> 1);
    const int bp   = ks & 1;            // output batch-pair
    const int et   = w8 * 32 + lane;    // 0..255 per dir (stage index)
    const int kst  = et >> 2, bst = et & 3;

    // ---- per-thread weights in registers ----
    float wx[2][4], wh0l[2][8], wy[2][16], wh1l[2][8];
    float bias0v, bias1v;
    {
        const int gr0 = dir * 128 + row0, gr1 = gr0 + 1;
#pragma unroll
        for (int i = 0; i < 4; ++i) {
            int c = ks * 4 + i;
            wx[0][i] = (c < DD) ? Wih0[gr0 * DD + c] : 0.0f;
            wx[1][i] = (c < DD) ? Wih0[gr1 * DD + c] : 0.0f;
        }
#pragma unroll
        for (int i = 0; i < 8; ++i) {
            int c = ks * 8 + i;
            wh0l[0][i] = Whh0[gr0 * HH + c];
            wh0l[1][i] = Whh0[gr1 * HH + c];
            wh1l[0][i] = Whh1[gr0 * HH + c];
            wh1l[1][i] = Whh1[gr1 * HH + c];
        }
#pragma unroll
        for (int i = 0; i < 16; ++i) {
            int c = ks * 16 + i;
            wy[0][i] = Wih1[gr0 * 64 + c];
            wy[1][i] = Wih1[gr1 * 64 + c];
        }
        bias0v = b0[dir * 128 + rowOut];
        bias1v = b1[dir * 128 + rowOut];
    }
    const float wfc = W_fc[lane];
    const float bfc = b_fc[0];

    // ---- initial states + pad init ----
    for (int e = tid; e < 4 * HH * BT; e += TPB) {
        int ld = e >> 7, k = (e >> 2) & 31, b = e & 3;
        sH[(ld * HH + k) * BT + b]   = h0[((size_t)ld * NB + bg + b) * HH + k];
        sCst[(ld * HH + k) * BT + b] = c0[((size_t)ld * NB + bg + b) * HH + k];
    }
    for (int e = tid; e < NC * BT; e += TPB) {
        int c = e >> 2, b = e & 3;
        sXN[c * BT + b] = rain_hist[((size_t)(bg + b) * NHIST + (NHIST - 1)) * NC + c];
        sX[(c * 16 + 15) * BT + b] = 0.0f;   // pad slot, stays zero
    }
    __syncthreads();

    for (int t = 0; t < NPRED; ++t) {
        // ============ Phase 1: build x tile (slot0=g, slot1=xn, 2..14=feat) ============
        for (int e = tid; e < NC * NFEAT * BT; e += TPB) {
            int b = e / (NC * NFEAT);
            int rem = e - b * (NC * NFEAT);
            int c = rem / NFEAT;
            int kk = rem - c * NFEAT;
            sX[(c * 16 + 2 + kk) * BT + b] =
                feature[(((size_t)(bg + b) * FTOT + NHIST + t) * NC + c) * NFEAT + kk];
        }
        for (int e = tid; e < NC * BT; e += TPB) {
            int c = e >> 2, b = e & 3;
            sX[(c * 16 + 1) * BT + b] = sXN[c * BT + b];
        }
        __syncthreads();

        // ============ Phase 2: gated graph MLP (c-split halves) ============
        if (tid < 368) {
            const int j = tid >> 1, ch = tid & 1;
            u64 a01 = (ch == 0) ? pk2(b_mlp[j]) : pk2(0.0f);
            u64 a23 = a01;
            const float* wbase = W_mlp + j;
            for (int c = ch * 92; c < ch * 92 + 92; ++c) {
                const ulonglong2* xp = (const ulonglong2*)(sX + (c * 16 + 1) * BT);
                const float* wp = wbase + (size_t)c * IND * NC;
#pragma unroll
                for (int kk = 0; kk < IND; ++kk) {
                    u64 w = pk2(wp[(size_t)kk * NC]);
                    ulonglong2 xv = xp[kk];
                    ffma2(a01, xv.x, w);
                    ffma2(a23, xv.y, w);
                }
            }
            float2 v01 = unpk(a01), v23 = unpk(a23);
            float4* mp = (float4*)(sMP + (ch * NC + j) * 4);
            *mp = make_float4(v01.x, v01.y, v23.x, v23.y);
        }
        __syncthreads();
        if (tid < NC) {
            const int j = tid;
#pragma unroll
            for (int b = 0; b < 4; ++b) {
                float a = sMP[j * 4 + b] + sMP[(NC + j) * 4 + b];
                sX[(j * 16) * BT + b] = sigf(a);
            }
        }
        __syncthreads();

        // ============ Phase 3: GRU cell ============
        for (int e = tid; e < BT * DD; e += TPB) {
            int b = e / DD, k = e - b * DD;
            float s = 0.0f;
            for (int c = 0; c < NC; ++c) s += sX[(c * 16 + k) * BT + b];
            sU[b * 16 + k] = s * (1.0f / NC);
        }
        __syncthreads();
        for (int e = tid; e < BT * 96; e += TPB) {
            int b = e / 96, j = e - b * 96;
            float a = b_ih_g[j];
#pragma unroll
            for (int k = 0; k < DD; ++k)
                a = fmaf(sU[b * 16 + k], Wih_g[k * 96 + j], a);
            sGX[e] = a;
        }
        for (int e = tid; e < 16 * 96; e += TPB) {
            int lb = e / 96, j = e - lb * 96;
            int l = lb >> 2, b = lb & 3;
            float a = b_hh_g[j];
#pragma unroll
            for (int k = 0; k < HH; ++k)
                a = fmaf(sH[(l * HH + k) * BT + b], Whh_g[k * 96 + j], a);
            sGH[e] = a;
        }
        __syncthreads();
        for (int e = tid; e < 4 * BT * HH; e += TPB) {
            int l = e >> 7, b = (e >> 5) & 3, j = e & 31;
            int gb = b * 96, ghb = (l * BT + b) * 96;
            float r = sigf(sGX[gb + j]      + sGH[ghb + j]);
            float z = sigf(sGX[gb + 32 + j] + sGH[ghb + 32 + j]);
            float n = tanhfast(sGX[gb + 64 + j] + r * sGH[ghb + 64 + j]);
            int hi = (l * HH + j) * BT + b;
            sH[hi] = (1.0f - z) * n + z * sH[hi];
        }
        __syncthreads();

        // ============ Phase 4: BiLSTM layer 0 ============
        {
            u64 a0, a1, a2, a3;
            // x-part prologue for s = 0
            {
                int city = dir ? (NC - 1) : 0;
                const ulonglong2* xp = (const ulonglong2*)sX + city * 16 + ks * 4;
                a0 = a1 = a2 = a3 = 0ULL;
#pragma unroll
                for (int i = 0; i < 4; ++i) {
                    ulonglong2 xv = xp[i];
                    u64 wA = pk2(wx[0][i]), wB = pk2(wx[1][i]);
                    ffma2(a0, xv.x, wA); ffma2(a1, xv.y, wA);
                    ffma2(a2, xv.x, wB); ffma2(a3, xv.y, wB);
                }
            }
            for (int s = 0; s < NC; ++s) {
                const int city = dir ? (NC - 1 - s) : s;
                // h-part
                const ulonglong2* hp = (const ulonglong2*)(sH + dir * HH * BT) + ks * 8;
#pragma unroll
                for (int i = 0; i < 8; ++i) {
                    ulonglong2 hv = hp[i];
                    u64 wA = pk2(wh0l[0][i]), wB = pk2(wh0l[1][i]);
                    ffma2(a0, hv.x, wA); ffma2(a1, hv.y, wA);
                    ffma2(a2, hv.x, wB); ffma2(a3, hv.y, wB);
                }
                u64 res = redscat(a0, a1, a2, a3, ks, bias0v);
                sGPq[(dir * 2 + bp) * 128 + rowOut] = res;
                dbar(dir);
                // overlap zone: update(s) on warps 0-3; x-part(s+1) on all
                if (w8 < 4) {
                    const int b = w8, j = lane;
                    const float* gf = sGPf + ((dir * 2 + (b >> 1)) * 128) * 2 + (b & 1);
                    float iv = sigf(gf[j * 2]);
                    float fv = sigf(gf[(32 + j) * 2]);
                    float gv = tanhfast(gf[(64 + j) * 2]);
                    float ov = sigf(gf[(96 + j) * 2]);
                    int ci = (dir * HH + j) * BT + b;
                    float cc = fmaf(fv, sCst[ci], iv * gv);
                    sCst[ci] = cc;
                    float hh2 = ov * tanhfast(cc);
                    sH[ci] = hh2;
                    g_y0[((size_t)(cta * NC + city) * BT + b) * 64 + dir * HH + j] = hh2;
                }
                if (s + 1 < NC) {
                    int cityn = dir ? (NC - 2 - s) : (s + 1);
                    const ulonglong2* xp = (const ulonglong2*)sX + cityn * 16 + ks * 4;
                    a0 = a1 = a2 = a3 = 0ULL;
#pragma unroll
                    for (int i = 0; i < 4; ++i) {
                        ulonglong2 xv = xp[i];
                        u64 wA = pk2(wx[0][i]), wB = pk2(wx[1][i]);
                        ffma2(a0, xv.x, wA); ffma2(a1, xv.y, wA);
                        ffma2(a2, xv.x, wB); ffma2(a3, xv.y, wB);
                    }
                }
                dbar(dir);
            }
        }
        __syncthreads();   // all y0 written before L1 staging

        // ============ Phase 5: BiLSTM layer 1 ============
        {
            u64 a0, a1, a2, a3;
            float pf;
            // prologue: stage input(0), prefetch input(1)
            {
                int c0_ = dir ? (NC - 1) : 0;
                sXin[dir * 256 + et] =
                    g_y0[((size_t)(cta * NC + c0_) * BT + bst) * 64 + kst];
                int c1_ = dir ? (NC - 2) : 1;
                pf = g_y0[((size_t)(cta * NC + c1_) * BT + bst) * 64 + kst];
            }
            dbar(dir);
            // x-part(0)
            {
                const ulonglong2* xp = (const ulonglong2*)sXin + dir * 64 + ks * 16;
                a0 = a1 = a2 = a3 = 0ULL;
#pragma unroll
                for (int i = 0; i < 16; ++i) {
                    ulonglong2 xv = xp[i];
                    u64 wA = pk2(wy[0][i]), wB = pk2(wy[1][i]);
                    ffma2(a0, xv.x, wA); ffma2(a1, xv.y, wA);
                    ffma2(a2, xv.x, wB); ffma2(a3, xv.y, wB);
                }
            }
            dbar(dir);
            for (int s = 0; s < NC; ++s) {
                // stash input(s+1) (prefetched last iter / prologue)
                if (s + 1 < NC) sXin[dir * 256 + et] = pf;
                // h-part
                const ulonglong2* hp = (const ulonglong2*)(sH + (2 + dir) * HH * BT) + ks * 8;
#pragma unroll
                for (int i = 0; i < 8; ++i) {
                    ulonglong2 hv = hp[i];
                    u64 wA = pk2(wh1l[0][i]), wB = pk2(wh1l[1][i]);
                    ffma2(a0, hv.x, wA); ffma2(a1, hv.y, wA);
                    ffma2(a2, hv.x, wB); ffma2(a3, hv.y, wB);
                }
                u64 res = redscat(a0, a1, a2, a3, ks, bias1v);
                sGPq[(dir * 2 + bp) * 128 + rowOut] = res;
                // prefetch input(s+2)
                if (s + 2 < NC) {
                    int cp = dir ? (NC - 3 - s) : (s + 2);
                    pf = g_y0[((size_t)(cta * NC + cp) * BT + bst) * 64 + kst];
                }
                dbar(dir);
                // overlap: update(s) + x-part(s+1)
                if (w8 < 4) {
                    const int b = w8, j = lane;
                    const float* gf = sGPf + ((dir * 2 + (b >> 1)) * 128) * 2 + (b & 1);
                    float iv = sigf(gf[j * 2]);
                    float fv = sigf(gf[(32 + j) * 2]);
                    float gv = tanhfast(gf[(64 + j) * 2]);
                    float ov = sigf(gf[(96 + j) * 2]);
                    int ci = ((2 + dir) * HH + j) * BT + b;
                    float cc = fmaf(fv, sCst[ci], iv * gv);
                    sCst[ci] = cc;
                    float hh2 = ov * tanhfast(cc);
                    sH[ci] = hh2;
                    if (dir == 0) {
                        // inline FC head
                        float v = wfc * hh2;
                        v += __shfl_xor_sync(0xffffffffu, v, 16);
                        v += __shfl_xor_sync(0xffffffffu, v, 8);
                        v += __shfl_xor_sync(0xffffffffu, v, 4);
                        v += __shfl_xor_sync(0xffffffffu, v, 2);
                        v += __shfl_xor_sync(0xffffffffu, v, 1);
                        if (j == 0) {
                            float a = v + bfc;
                            sXN[s * BT + b] = a;
                            out[((size_t)(bg + b) * NPRED + t) * NC + s] = a;
                        }
                    }
                }
                if (s + 1 < NC) {
                    const ulonglong2* xp = (const ulonglong2*)sXin + dir * 64 + ks * 16;
                    a0 = a1 = a2 = a3 = 0ULL;
#pragma unroll
                    for (int i = 0; i < 16; ++i) {
                        ulonglong2 xv = xp[i];
                        u64 wA = pk2(wy[0][i]), wB = pk2(wy[1][i]);
                        ffma2(a0, xv.x, wA); ffma2(a1, xv.y, wA);
                        ffma2(a2, xv.x, wB); ffma2(a3, xv.y, wB);
                    }
                }
                dbar(dir);
            }
        }
        __syncthreads();
    }
}

extern "C" void kernel_launch(void* const* d_in, const int* in_sizes, int n_in,
                              void* d_out, int out_size) {
    (void)in_sizes; (void)n_in; (void)out_size;
    const float* rain_hist = (const float*)d_in[0];
    const float* feature   = (const float*)d_in[1];
    const float* h0        = (const float*)d_in[2];
    const float* c0        = (const float*)d_in[3];
    const float* W_mlp     = (const float*)d_in[4];
    const float* b_mlp     = (const float*)d_in[5];
    const float* Wih_g     = (const float*)d_in[6];
    const float* Whh_g     = (const float*)d_in[7];
    const float* b_ih_g    = (const float*)d_in[8];
    const float* b_hh_g    = (const float*)d_in[9];
    const float* Wih0      = (const float*)d_in[10];
    const float* Whh0      = (const float*)d_in[11];
    const float* b0        = (const float*)d_in[12];
    const float* Wih1      = (const float*)d_in[13];
    const float* Whh1      = (const float*)d_in[14];
    const float* b1        = (const float*)d_in[15];
    const float* W_fc      = (const float*)d_in[16];
    const float* b_fc      = (const float*)d_in[17];

    size_t smem = (size_t)SMEM_FLOATS * sizeof(float);
    cudaFuncSetAttribute(bilstm_kernel,
                         cudaFuncAttributeMaxDynamicSharedMemorySize, (int)smem);

    bilstm_kernel<<<NCTA, TPB, smem>>>(
        rain_hist, feature, h0, c0, W_mlp, b_mlp,
        Wih_g, Whh_g, b_ih_g, b_hh_g,
        Wih0, Whh0, b0, Wih1, Whh1, b1,
        W_fc, b_fc, (float*)d_out);
}

// round 5
// speedup vs baseline: 2.5402x; 2.5402x over previous
#include <cuda_runtime.h>

// Problem constants
#define NCTA   128
#define TPB    256
#define NB     512
#define BT     4       // batch elements per CTA
#define NC     184     // cities
#define HH     32      // hidden
#define IND    14      // in_dim
#define DD     15      // in_dim + 1
#define NPRED  24
#define NHIST  24
#define NFEAT  13      // in_dim - 1
#define FTOT   48      // hist + pred

// Global scratch (per-CTA private slices)
__device__ float g_y0[(size_t)NCTA * NC * BT * HH];          // fwd y0 only
__device__ float g_pre[(size_t)NCTA * NPRED * NC * BT];      // MLP feature part

// Shared memory layout (float offsets; 16B alignment where vector-loaded)
#define OFF_X    0        // 184*16*4 = 11776   x tile [c][k16][b]
#define OFF_Y0B  11776    // 184*32*4 = 23552   bwd y0 [c][k][b]
#define OFF_XIN  35328    // 2dir*2buf*128      staged fwd y0 [k][b]
#define OFF_G    35840    // 2*4*128  = 1024    gate buffer [dir][b][row]
#define OFF_H    36864    // 4*32*4   = 512     h state [ld][k][b]
#define OFF_C    37376    // 4*32*4   = 512     c state [ld][k][b]
#define OFF_XN   37888    // 184*4    = 736     xn [c][b]
#define OFF_GX   38624    // 4*96
#define OFF_GH   39008    // 16*96
#define OFF_U    40544    // 4*16
#define SMEM_FLOATS 40608 // 162,432 bytes

typedef unsigned long long u64;

__device__ __forceinline__ u64 pk2(float w) {
    u64 r; asm("mov.b64 %0, {%1, %1};" : "=l"(r) : "f"(w)); return r;
}
__device__ __forceinline__ u64 pack2(float a, float b) {
    u64 r; asm("mov.b64 %0, {%1, %2};" : "=l"(r) : "f"(a), "f"(b)); return r;
}
__device__ __forceinline__ void ffma2(u64& a, u64 x, u64 w) {
    asm("fma.rn.f32x2 %0, %1, %2, %0;" : "+l"(a) : "l"(x), "l"(w));
}
__device__ __forceinline__ u64 addx2(u64 a, u64 b) {
    u64 r; asm("add.rn.f32x2 %0, %1, %2;" : "=l"(r) : "l"(a), "l"(b)); return r;
}
__device__ __forceinline__ float2 unpk(u64 a) {
    float2 f; asm("mov.b64 {%0, %1}, %2;" : "=f"(f.x), "=f"(f.y) : "l"(a)); return f;
}
__device__ __forceinline__ float sigf(float x) {
    return __fdividef(1.0f, 1.0f + __expf(-x));
}
__device__ __forceinline__ float tanhfast(float x) {
    x = fminf(fmaxf(x, -15.0f), 15.0f);
    float e = __expf(2.0f * x);
    return __fdividef(e - 1.0f, e + 1.0f);
}

// ===================== Pre-pass: MLP feature part for all t =====================
#define TPP 192
__global__ void __launch_bounds__(TPP, 1)
pre_mlp_kernel(const float* __restrict__ feature, const float* __restrict__ W_mlp)
{
    __shared__ float ft[2][13 * 96];   // [kk][t][b]
    const int tid = threadIdx.x;
    const int cta = blockIdx.x;
    const int bg  = cta * BT;

    u64 A[NPRED], B[NPRED];
#pragma unroll
    for (int tt = 0; tt < NPRED; ++tt) { A[tt] = 0ULL; B[tt] = 0ULL; }

    // stage c = 0
    for (int e = tid; e < 13 * 96; e += TPP) {
        int kk = e / 96, r = e - kk * 96, tt = r >> 2, b = r & 3;
        ft[0][e] = feature[(((size_t)(bg + b) * FTOT + NHIST + tt) * NC + 0) * NFEAT + kk];
    }
    __syncthreads();

    for (int c = 0; c < NC; ++c) {
        const int p = c & 1;
        // prefetch c+1 into regs
        float pfv[7];
        if (c + 1 < NC) {
#pragma unroll
            for (int q = 0; q < 7; ++q) {
                int e = tid + q * TPP;
                if (e < 13 * 96) {
                    int kk = e / 96, r = e - kk * 96, tt = r >> 2, b = r & 3;
                    pfv[q] = feature[(((size_t)(bg + b) * FTOT + NHIST + tt) * NC + (c + 1)) * NFEAT + kk];
                }
            }
        }
        if (tid < NC) {
            float wv[13];
#pragma unroll
            for (int kk = 0; kk < 13; ++kk)
                wv[kk] = W_mlp[((size_t)c * IND + 1 + kk) * NC + tid];
#pragma unroll
            for (int kk = 0; kk < 13; ++kk) {
                u64 w2 = pk2(wv[kk]);
#pragma unroll
                for (int tt = 0; tt < NPRED; ++tt) {
                    ulonglong2 f2 = *(const ulonglong2*)&ft[p][kk * 96 + tt * 4];
                    ffma2(A[tt], f2.x, w2);
                    ffma2(B[tt], f2.y, w2);
                }
            }
        }
        if (c + 1 < NC) {
#pragma unroll
            for (int q = 0; q < 7; ++q) {
                int e = tid + q * TPP;
                if (e < 13 * 96) ft[p ^ 1][e] = pfv[q];
            }
        }
        __syncthreads();
    }
    if (tid < NC) {
#pragma unroll
        for (int tt = 0; tt < NPRED; ++tt) {
            float2 fa = unpk(A[tt]), fb = unpk(B[tt]);
            *(float4*)&g_pre[(((size_t)cta * NPRED + tt) * NC + tid) * 4] =
                make_float4(fa.x, fa.y, fb.x, fb.y);
        }
    }
}

// ===================== Main persistent kernel =====================
__global__ void __launch_bounds__(TPB, 1)
bilstm_kernel(const float* __restrict__ rain_hist,
              const float* __restrict__ feature,
              const float* __restrict__ h0,
              const float* __restrict__ c0,
              const float* __restrict__ W_mlp,
              const float* __restrict__ b_mlp,
              const float* __restrict__ Wih_g,
              const float* __restrict__ Whh_g,
              const float* __restrict__ b_ih_g,
              const float* __restrict__ b_hh_g,
              const float* __restrict__ Wih0,
              const float* __restrict__ Whh0,
              const float* __restrict__ b0,
              const float* __restrict__ Wih1,
              const float* __restrict__ Whh1,
              const float* __restrict__ b1,
              const float* __restrict__ W_fc,
              const float* __restrict__ b_fc,
              float* __restrict__ out)
{
    extern __shared__ float sm[];
    float* sX   = sm + OFF_X;
    float* sY0B = sm + OFF_Y0B;
    float* sXin = sm + OFF_XIN;
    float* sG   = sm + OFF_G;
    float* sH   = sm + OFF_H;
    float* sCst = sm + OFF_C;
    float* sXN  = sm + OFF_XN;
    float* sGX  = sm + OFF_GX;
    float* sGH  = sm + OFF_GH;
    float* sU   = sm + OFF_U;

    const int tid  = threadIdx.x;
    const int cta  = blockIdx.x;
    const int bg   = cta * BT;
    const int dirg = tid >> 7;          // gate-phase direction
    const int jg   = tid & 127;         // gate row within dir
    const int bu   = (tid >> 5) & 3;    // update-phase batch
    const int ju   = tid & 31;          // update-phase hidden idx
    const int row  = dirg * 128 + jg;
    const int loc  = tid & 127;         // staging index within dir
    const int kst  = loc & 31, bst = loc >> 5;

    // ---- per-thread weight rows in registers ----
    float w0x[DD], w0h[HH], w1f[HH], w1b[HH], w1h[HH], bias0, bias1;
#pragma unroll
    for (int k = 0; k < DD; ++k) w0x[k] = Wih0[row * DD + k];
#pragma unroll
    for (int k = 0; k < HH; ++k) w0h[k] = Whh0[row * HH + k];
    bias0 = b0[row];
#pragma unroll
    for (int k = 0; k < HH; ++k) w1f[k] = Wih1[row * 64 + k];
#pragma unroll
    for (int k = 0; k < HH; ++k) w1b[k] = Wih1[row * 64 + 32 + k];
#pragma unroll
    for (int k = 0; k < HH; ++k) w1h[k] = Whh1[row * HH + k];
    bias1 = b1[row];
    const float wfc = W_fc[ju];
    const float bfc = b_fc[0];

    // ---- initial states ----
    for (int e = tid; e < 4 * HH * BT; e += TPB) {
        int ld = e >> 7, k = (e >> 2) & 31, b = e & 3;
        sH[(ld * HH + k) * BT + b]   = h0[((size_t)ld * NB + bg + b) * HH + k];
        sCst[(ld * HH + k) * BT + b] = c0[((size_t)ld * NB + bg + b) * HH + k];
    }
    for (int e = tid; e < NC * BT; e += TPB) {
        int c = e >> 2, b = e & 3;
        sXN[c * BT + b] = rain_hist[((size_t)(bg + b) * NHIST + (NHIST - 1)) * NC + c];
    }
    __syncthreads();

    for (int t = 0; t < NPRED; ++t) {
        // ============ Phase 1: build x tile (slot0=g, slot1=xn, 2..14=feat) ============
        for (int e = tid; e < NC * NFEAT * BT; e += TPB) {
            int b = e / (NC * NFEAT);
            int rem = e - b * (NC * NFEAT);
            int c = rem / NFEAT;
            int kk = rem - c * NFEAT;
            sX[(c * 16 + 2 + kk) * BT + b] =
                feature[(((size_t)(bg + b) * FTOT + NHIST + t) * NC + c) * NFEAT + kk];
        }
        for (int e = tid; e < NC * BT; e += TPB) {
            int c = e >> 2, b = e & 3;
            sX[(c * 16 + 1) * BT + b] = sXN[c * BT + b];
        }
        __syncthreads();

        // ============ Phase 2: MLP = precomputed feat part + rank-1 xn part ============
        if (tid < NC) {
            const int j = tid;
            float4 pre4 = *(const float4*)(g_pre + (((size_t)cta * NPRED + t) * NC + j) * 4);
            u64 A[4], B[4];
            A[0] = pack2(pre4.x, pre4.y); B[0] = pack2(pre4.z, pre4.w);
#pragma unroll
            for (int q = 1; q < 4; ++q) { A[q] = 0ULL; B[q] = 0ULL; }
            for (int c = 0; c < NC; c += 4) {
#pragma unroll
                for (int q = 0; q < 4; ++q) {
                    float w = W_mlp[((size_t)(c + q) * IND) * NC + j];
                    ulonglong2 xv = *(const ulonglong2*)(sXN + (c + q) * 4);
                    u64 w2 = pk2(w);
                    ffma2(A[q], xv.x, w2);
                    ffma2(B[q], xv.y, w2);
                }
            }
            u64 a01 = addx2(addx2(A[0], A[1]), addx2(A[2], A[3]));
            u64 a23 = addx2(addx2(B[0], B[1]), addx2(B[2], B[3]));
            a01 = addx2(a01, pk2(b_mlp[j]));
            a23 = addx2(a23, pk2(b_mlp[j]));
            float2 v01 = unpk(a01), v23 = unpk(a23);
            sX[(j * 16) * BT + 0] = sigf(v01.x);
            sX[(j * 16) * BT + 1] = sigf(v01.y);
            sX[(j * 16) * BT + 2] = sigf(v23.x);
            sX[(j * 16) * BT + 3] = sigf(v23.y);
        }
        __syncthreads();

        // ============ Phase 3: GRU cell ============
        for (int e = tid; e < BT * DD; e += TPB) {
            int b = e / DD, k = e - b * DD;
            float s = 0.0f;
            for (int c = 0; c < NC; ++c) s += sX[(c * 16 + k) * BT + b];
            sU[b * 16 + k] = s * (1.0f / NC);
        }
        __syncthreads();
        for (int e = tid; e < BT * 96; e += TPB) {
            int b = e / 96, j = e - b * 96;
            float a = b_ih_g[j];
#pragma unroll
            for (int k = 0; k < DD; ++k)
                a = fmaf(sU[b * 16 + k], Wih_g[k * 96 + j], a);
            sGX[e] = a;
        }
        for (int e = tid; e < 16 * 96; e += TPB) {
            int lb = e / 96, j = e - lb * 96;
            int l = lb >> 2, b = lb & 3;
            float a = b_hh_g[j];
#pragma unroll
            for (int k = 0; k < HH; ++k)
                a = fmaf(sH[(l * HH + k) * BT + b], Whh_g[k * 96 + j], a);
            sGH[e] = a;
        }
        __syncthreads();
        for (int e = tid; e < 4 * BT * HH; e += TPB) {
            int l = e >> 7, b = (e >> 5) & 3, j = e & 31;
            int gb = b * 96, ghb = (l * BT + b) * 96;
            float r = sigf(sGX[gb + j]      + sGH[ghb + j]);
            float z = sigf(sGX[gb + 32 + j] + sGH[ghb + 32 + j]);
            float n = tanhfast(sGX[gb + 64 + j] + r * sGH[ghb + 64 + j]);
            int hi = (l * HH + j) * BT + b;
            sH[hi] = (1.0f - z) * n + z * sH[hi];
        }
        __syncthreads();

        // ============ Phase 4: BiLSTM layer 0 (x-part pipelined into update window) ====
        {
            const ulonglong2* hp = (const ulonglong2*)(sH + dirg * HH * BT);
            u64 a01, a23;
            // x-acc prologue for s = 0
            {
                int city = dirg ? (NC - 1) : 0;
                const ulonglong2* xp = (const ulonglong2*)(sX + city * 16 * BT);
                a01 = pk2(bias0); a23 = a01;
#pragma unroll
                for (int k = 0; k < DD; ++k) {
                    u64 w = pk2(w0x[k]);
                    ulonglong2 xv = xp[k];
                    ffma2(a01, xv.x, w); ffma2(a23, xv.y, w);
                }
            }
            for (int s = 0; s < NC; ++s) {
                // h-part
#pragma unroll
                for (int k = 0; k < HH; ++k) {
                    u64 w = pk2(w0h[k]);
                    ulonglong2 hv = hp[k];
                    ffma2(a01, hv.x, w); ffma2(a23, hv.y, w);
                }
                float2 v01 = unpk(a01), v23 = unpk(a23);
                float* gp = sG + dirg * 512 + jg;
                gp[0] = v01.x; gp[128] = v01.y; gp[256] = v23.x; gp[384] = v23.y;
                __syncthreads();
                // window: update(s) + x-acc(s+1)
                {
                    const int du = tid >> 7;
                    const float* g = sG + du * 512 + bu * 128;
                    float iv = sigf(g[ju]);
                    float fv = sigf(g[32 + ju]);
                    float gv = tanhfast(g[64 + ju]);
                    float ov = sigf(g[96 + ju]);
                    int ci = (du * HH + ju) * BT + bu;
                    float cc = fmaf(fv, sCst[ci], iv * gv);
                    sCst[ci] = cc;
                    float hh2 = ov * tanhfast(cc);
                    sH[ci] = hh2;
                    int cityu = du ? (NC - 1 - s) : s;
                    if (du == 0)
                        g_y0[((size_t)(cta * NC + cityu) * BT + bu) * HH + ju] = hh2;
                    else
                        sY0B[cityu * 128 + ju * 4 + bu] = hh2;
                }
                if (s + 1 < NC) {
                    int cityn = dirg ? (NC - 2 - s) : (s + 1);
                    const ulonglong2* xp = (const ulonglong2*)(sX + cityn * 16 * BT);
                    a01 = pk2(bias0); a23 = a01;
#pragma unroll
                    for (int k = 0; k < DD; ++k) {
                        u64 w = pk2(w0x[k]);
                        ulonglong2 xv = xp[k];
                        ffma2(a01, xv.x, w); ffma2(a23, xv.y, w);
                    }
                }
                __syncthreads();
            }
        }
        __syncthreads();   // all y0 visible (global fence at block scope)

        // ============ Phase 5: BiLSTM layer 1 ============
        {
            const ulonglong2* hp = (const ulonglong2*)(sH + (2 + dirg) * HH * BT);
            u64 a01, a23;
            float pf;
            // prologue: stage y0f(0), prefetch y0f(1), compute y0b-part(0)
            {
                int c0_ = dirg ? (NC - 1) : 0;
                sXin[(dirg * 2 + 0) * 128 + kst * 4 + bst] =
                    g_y0[((size_t)(cta * NC + c0_) * BT + bst) * HH + kst];
                int c1_ = dirg ? (NC - 2) : 1;
                pf = g_y0[((size_t)(cta * NC + c1_) * BT + bst) * HH + kst];
            }
            {
                int city = dirg ? (NC - 1) : 0;
                const ulonglong2* bp2 = (const ulonglong2*)(sY0B + city * 128);
                a01 = pk2(bias1); a23 = a01;
#pragma unroll
                for (int k = 0; k < HH; ++k) {
                    u64 w = pk2(w1b[k]);
                    ulonglong2 bv = bp2[k];
                    ffma2(a01, bv.x, w); ffma2(a23, bv.y, w);
                }
            }
            __syncthreads();
            int buf = 0;
            for (int s = 0; s < NC; ++s) {
                // gate: y0f-part (staged) + h-part
                const ulonglong2* fp2 = (const ulonglong2*)(sXin + (dirg * 2 + buf) * 128);
#pragma unroll
                for (int k = 0; k < HH; ++k) {
                    u64 w = pk2(w1f[k]);
                    ulonglong2 fv2 = fp2[k];
                    ffma2(a01, fv2.x, w); ffma2(a23, fv2.y, w);
                }
#pragma unroll
                for (int k = 0; k < HH; ++k) {
                    u64 w = pk2(w1h[k]);
                    ulonglong2 hv = hp[k];
                    ffma2(a01, hv.x, w); ffma2(a23, hv.y, w);
                }
                float2 v01 = unpk(a01), v23 = unpk(a23);
                float* gp = sG + dirg * 512 + jg;
                gp[0] = v01.x; gp[128] = v01.y; gp[256] = v23.x; gp[384] = v23.y;
                __syncthreads();
                // window: stash y0f(s+1), prefetch y0f(s+2), update(s), y0b-part(s+1)
                if (s + 1 < NC)
                    sXin[(dirg * 2 + (buf ^ 1)) * 128 + kst * 4 + bst] = pf;
                if (s + 2 < NC) {
                    int cp = dirg ? (NC - 3 - s) : (s + 2);
                    pf = g_y0[((size_t)(cta * NC + cp) * BT + bst) * HH + kst];
                }
                {
                    const int du = tid >> 7;
                    const float* g = sG + du * 512 + bu * 128;
                    float iv = sigf(g[ju]);
                    float fv = sigf(g[32 + ju]);
                    float gv = tanhfast(g[64 + ju]);
                    float ov = sigf(g[96 + ju]);
                    int ci = ((2 + du) * HH + ju) * BT + bu;
                    float cc = fmaf(fv, sCst[ci], iv * gv);
                    sCst[ci] = cc;
                    float hh2 = ov * tanhfast(cc);
                    sH[ci] = hh2;
                    if (du == 0) {
                        // inline FC head (fwd half only)
                        float v = wfc * hh2;
                        v += __shfl_xor_sync(0xffffffffu, v, 16);
                        v += __shfl_xor_sync(0xffffffffu, v, 8);
                        v += __shfl_xor_sync(0xffffffffu, v, 4);
                        v += __shfl_xor_sync(0xffffffffu, v, 2);
                        v += __shfl_xor_sync(0xffffffffu, v, 1);
                        if (ju == 0) {
                            float a = v + bfc;
                            sXN[s * BT + bu] = a;
                            out[((size_t)(bg + bu) * NPRED + t) * NC + s] = a;
                        }
                    }
                }
                if (s + 1 < NC) {
                    int cityn = dirg ? (NC - 2 - s) : (s + 1);
                    const ulonglong2* bp2 = (const ulonglong2*)(sY0B + cityn * 128);
                    a01 = pk2(bias1); a23 = a01;
#pragma unroll
                    for (int k = 0; k < HH; ++k) {
                        u64 w = pk2(w1b[k]);
                        ulonglong2 bv = bp2[k];
                        ffma2(a01, bv.x, w); ffma2(a23, bv.y, w);
                    }
                }
                __syncthreads();
                buf ^= 1;
            }
        }
        __syncthreads();
    }
}

extern "C" void kernel_launch(void* const* d_in, const int* in_sizes, int n_in,
                              void* d_out, int out_size) {
    (void)in_sizes; (void)n_in; (void)out_size;
    const float* rain_hist = (const float*)d_in[0];
    const float* feature   = (const float*)d_in[1];
    const float* h0        = (const float*)d_in[2];
    const float* c0        = (const float*)d_in[3];
    const float* W_mlp     = (const float*)d_in[4];
    const float* b_mlp     = (const float*)d_in[5];
    const float* Wih_g     = (const float*)d_in[6];
    const float* Whh_g     = (const float*)d_in[7];
    const float* b_ih_g    = (const float*)d_in[8];
    const float* b_hh_g    = (const float*)d_in[9];
    const float* Wih0      = (const float*)d_in[10];
    const float* Whh0      = (const float*)d_in[11];
    const float* b0        = (const float*)d_in[12];
    const float* Wih1      = (const float*)d_in[13];
    const float* Whh1      = (const float*)d_in[14];
    const float* b1        = (const float*)d_in[15];
    const float* W_fc      = (const float*)d_in[16];
    const float* b_fc      = (const float*)d_in[17];

    pre_mlp_kernel<<<NCTA, TPP>>>(feature, W_mlp);

    size_t smem = (size_t)SMEM_FLOATS * sizeof(float);
    cudaFuncSetAttribute(bilstm_kernel,
                         cudaFuncAttributeMaxDynamicSharedMemorySize, (int)smem);
    bilstm_kernel<<<NCTA, TPB, smem>>>(
        rain_hist, feature, h0, c0, W_mlp, b_mlp,
        Wih_g, Whh_g, b_ih_g, b_hh_g,
        Wih0, Whh0, b0, Wih1, Whh1, b1,
        W_fc, b_fc, (float*)d_out);
}